// round 13
// baseline (speedup 1.0000x reference)
#include <cuda_runtime.h>
#include <cuda_fp16.h>
#include <cstdint>

#define B_TOK 65536
#define DIM   512
#define NCLS  1000
#define NEXP  3
#define SCALE_F 30.0f

#define TM 128
#define TN 128
#define KC 64
#define NCH (DIM / KC)   // 8 k-chunks
#define NSTG 3
#define A_STG_B 16384                       // A stage bytes (128 rows x 128B)
#define STG_BYTES 32768                     // A+B stage bytes
#define SMEM_DYN (NSTG * STG_BYTES + 128)   // 96 KB + align slack

// ---------------- device scratch (static allocation only) ----------------
__device__ __half g_fw[NEXP * NCLS * DIM];        // normalized fine weights, fp16, [e][c][d]
__device__ float  g_cw[NEXP * DIM];               // normalized coarse weights, fp32
__device__ __half g_nx[(size_t)B_TOK * DIM];      // normalized tokens, fp16
__device__ int    g_cnt[NEXP];                    // per-expert token counts
__device__ int    g_idx[NEXP * B_TOK];            // per-expert token index lists

// ---------------- kernel 0: normalize weights ----------------
__global__ void k_norm_w(const float* __restrict__ wc,
                         const float* __restrict__ w0,
                         const float* __restrict__ w1,
                         const float* __restrict__ w2) {
    int r = blockIdx.x;
    int t = threadIdx.x;
    if (r == 0 && t < NEXP) g_cnt[t] = 0;

    const float* src;
    bool fine = (r < NEXP * NCLS);
    if (fine) {
        int e = r / NCLS, c = r - e * NCLS;
        const float* w = (e == 0) ? w0 : ((e == 1) ? w1 : w2);
        src = w + (size_t)c * DIM;
    } else {
        src = wc + (size_t)(r - NEXP * NCLS) * DIM;
    }

    float v[4];
    float ss = 0.f;
    #pragma unroll
    for (int i = 0; i < 4; i++) {
        v[i] = src[t + i * 128];
        ss += v[i] * v[i];
    }
    #pragma unroll
    for (int o = 16; o > 0; o >>= 1) ss += __shfl_xor_sync(0xffffffffu, ss, o);
    __shared__ float red[4];
    if ((t & 31) == 0) red[t >> 5] = ss;
    __syncthreads();
    float tot = red[0] + red[1] + red[2] + red[3];
    float inv = 1.0f / sqrtf(fmaxf(tot, 1e-24f));

    if (fine) {
        __half* dst = g_fw + (size_t)r * DIM;
        #pragma unroll
        for (int i = 0; i < 4; i++) dst[t + i * 128] = __float2half_rn(v[i] * inv);
    } else {
        float* dst = g_cw + (size_t)(r - NEXP * NCLS) * DIM;
        #pragma unroll
        for (int i = 0; i < 4; i++) dst[t + i * 128] = v[i] * inv;
    }
}

// ---------------- kernel 1: coarse logits + routing + fp16 token convert ----------------
__global__ void k_coarse_route(const float* __restrict__ x, float* __restrict__ out,
                               long coarse_off, long sel_off) {
    int warp = threadIdx.x >> 5, lane = threadIdx.x & 31;
    int b = blockIdx.x * 8 + warp;

    const float4* xr = reinterpret_cast<const float4*>(x + (size_t)b * DIM);
    const float4* cw4 = reinterpret_cast<const float4*>(g_cw);

    float4 v[4];
    float ss = 0.f, d0 = 0.f, d1 = 0.f, d2 = 0.f;
    #pragma unroll
    for (int j = 0; j < 4; j++) {
        int o = j * 32 + lane;
        v[j] = xr[o];
        float4 c0 = cw4[o];
        float4 c1 = cw4[o + 128];
        float4 c2 = cw4[o + 256];
        ss += v[j].x * v[j].x + v[j].y * v[j].y + v[j].z * v[j].z + v[j].w * v[j].w;
        d0 += v[j].x * c0.x + v[j].y * c0.y + v[j].z * c0.z + v[j].w * c0.w;
        d1 += v[j].x * c1.x + v[j].y * c1.y + v[j].z * c1.z + v[j].w * c1.w;
        d2 += v[j].x * c2.x + v[j].y * c2.y + v[j].z * c2.z + v[j].w * c2.w;
    }
    #pragma unroll
    for (int o = 16; o > 0; o >>= 1) {
        ss += __shfl_xor_sync(0xffffffffu, ss, o);
        d0 += __shfl_xor_sync(0xffffffffu, d0, o);
        d1 += __shfl_xor_sync(0xffffffffu, d1, o);
        d2 += __shfl_xor_sync(0xffffffffu, d2, o);
    }
    float inv = 1.0f / sqrtf(fmaxf(ss, 1e-24f));
    float c0 = d0 * inv * SCALE_F;
    float c1 = d1 * inv * SCALE_F;
    float c2 = d2 * inv * SCALE_F;
    int sel = 0; float best = c0;
    if (c1 > best) { best = c1; sel = 1; }
    if (c2 > best) { sel = 2; }

    if (lane == 0) {
        if (coarse_off >= 0) {
            out[coarse_off + (size_t)b * 3 + 0] = c0;
            out[coarse_off + (size_t)b * 3 + 1] = c1;
            out[coarse_off + (size_t)b * 3 + 2] = c2;
        }
        if (sel_off >= 0) out[sel_off + b] = (float)sel;
        int pos = atomicAdd(&g_cnt[sel], 1);
        g_idx[sel * B_TOK + pos] = b;
    }

    __half2* dst = reinterpret_cast<__half2*>(g_nx + (size_t)b * DIM);
    #pragma unroll
    for (int j = 0; j < 4; j++) {
        int o = (j * 32 + lane) * 2;
        dst[o]     = __floats2half2_rn(v[j].x * inv, v[j].y * inv);
        dst[o + 1] = __floats2half2_rn(v[j].z * inv, v[j].w * inv);
    }
}

// ---------------- kernel 2: routed fp16 GEMM (merged experts, hoisted addressing) ----------------
__device__ __forceinline__ void cp16(uint32_t dst, const void* src) {
    asm volatile("cp.async.cg.shared.global [%0], [%1], 16;\n" :: "r"(dst), "l"(src));
}
__device__ __forceinline__ void cp_commit() { asm volatile("cp.async.commit_group;\n"); }
template <int N> __device__ __forceinline__ void cp_wait() {
    asm volatile("cp.async.wait_group %0;\n" :: "n"(N));
}
#define LDSM4(f, addr) \
    asm volatile("ldmatrix.sync.aligned.m8n8.x4.shared.b16 {%0,%1,%2,%3}, [%4];" \
        : "=r"((f)[0]), "=r"((f)[1]), "=r"((f)[2]), "=r"((f)[3]) : "r"(addr))

__global__ void __launch_bounds__(256, 2)
k_gemm(float* __restrict__ out, long out_off) {
    extern __shared__ __half sm[];
    __shared__ int srow[TM];

    int e = blockIdx.z;
    int cnt = g_cnt[e];
    int m0 = blockIdx.y * TM;
    if (m0 >= cnt) return;
    int n0 = blockIdx.x * TN;
    int mcnt = min(TM, cnt - m0);
    int tid = threadIdx.x;

    if (tid < TM) {
        int mi = m0 + tid;
        srow[tid] = g_idx[e * B_TOK + (mi < cnt ? mi : m0)];
    }
    __syncthreads();

    uint32_t sbase = (uint32_t)__cvta_generic_to_shared(sm);
    sbase = (sbase + 127u) & ~127u;        // 128B-align: XOR swizzle trick exact

    const __half* wbase = g_fw + (size_t)e * NCLS * DIM;

    // ---- hoisted producer addressing: fixed rows per thread, advance by KC per chunk ----
    const __half* asrc[4];
    const __half* bsrc[4];
    uint32_t adst[4], bdst[4];
    #pragma unroll
    for (int i = 0; i < 4; i++) {
        int id = tid + i * 256;
        int r = id >> 3, seg = id & 7;
        asrc[i] = g_nx + (size_t)srow[r] * DIM + seg * 8;
        adst[i] = r * 128 + ((seg ^ (r & 7)) << 4);
        int c = n0 + r; if (c >= NCLS) c = NCLS - 1;   // clamp, store-side guarded
        bsrc[i] = wbase + (size_t)c * DIM + seg * 8;
        bdst[i] = A_STG_B + r * 128 + ((seg ^ (r & 7)) << 4);
    }

    auto load_stage = [&](int s) {          // loads NEXT sequential chunk (ptrs auto-advance)
        uint32_t sa = sbase + s * STG_BYTES;
        #pragma unroll
        for (int i = 0; i < 4; i++) { cp16(sa + adst[i], asrc[i]); asrc[i] += KC; }
        #pragma unroll
        for (int i = 0; i < 4; i++) { cp16(sa + bdst[i], bsrc[i]); bsrc[i] += KC; }
    };

    load_stage(0);      cp_commit();        // chunk 0
    load_stage(1);      cp_commit();        // chunk 1

    int warp = tid >> 5, lane = tid & 31;
    int wm = (warp >> 1) * 32;   // 4 warps along M
    int wn = (warp & 1) * 64;    // 2 warps along N

    // per-thread base byte offsets within a stage (kk=0); per-kk addr = base ^ (kk*32)
    uint32_t aoff[2], boff[4];
    #pragma unroll
    for (int mt = 0; mt < 2; mt++) {
        int row = wm + mt * 16 + (lane & 15);
        int s = lane >> 4;
        aoff[mt] = row * 128 + ((s ^ (row & 7)) << 4);
    }
    #pragma unroll
    for (int bt = 0; bt < 4; bt++) {
        int sub = lane >> 3;
        int n = wn + bt * 16 + ((sub >> 1) << 3) + (lane & 7);
        int s = sub & 1;
        boff[bt] = A_STG_B + n * 128 + ((s ^ (n & 7)) << 4);
    }

    float acc[2][8][4];
    #pragma unroll
    for (int a = 0; a < 2; a++)
        #pragma unroll
        for (int b = 0; b < 8; b++)
            #pragma unroll
            for (int c = 0; c < 4; c++) acc[a][b][c] = 0.f;

    int stage = 0;
    for (int ch = 0; ch < NCH; ch++) {
        cp_wait<1>();
        __syncthreads();      // chunk ch resident; stage we write next is free

        // issue next-next chunk load into the stage freed last iteration
        if (ch + 2 < NCH) {
            int s2 = stage + 2; if (s2 >= NSTG) s2 -= NSTG;
            load_stage(s2);
        }
        cp_commit();          // unconditional: uniform group accounting

        uint32_t sb = sbase + stage * STG_BYTES;
        #pragma unroll
        for (int kk = 0; kk < 4; kk++) {
            uint32_t x = (uint32_t)kk << 5;
            uint32_t af[2][4], bf[4][4];
            #pragma unroll
            for (int mt = 0; mt < 2; mt++) LDSM4(af[mt], (sb + aoff[mt]) ^ x);
            #pragma unroll
            for (int bt = 0; bt < 4; bt++) LDSM4(bf[bt], (sb + boff[bt]) ^ x);
            #pragma unroll
            for (int mt = 0; mt < 2; mt++)
                #pragma unroll
                for (int nt = 0; nt < 8; nt++) {
                    uint32_t b0 = bf[nt >> 1][(nt & 1) * 2];
                    uint32_t b1 = bf[nt >> 1][(nt & 1) * 2 + 1];
                    asm volatile(
                        "mma.sync.aligned.m16n8k16.row.col.f32.f16.f16.f32 "
                        "{%0,%1,%2,%3}, {%4,%5,%6,%7}, {%8,%9}, {%0,%1,%2,%3};"
                        : "+f"(acc[mt][nt][0]), "+f"(acc[mt][nt][1]),
                          "+f"(acc[mt][nt][2]), "+f"(acc[mt][nt][3])
                        : "r"(af[mt][0]), "r"(af[mt][1]),
                          "r"(af[mt][2]), "r"(af[mt][3]),
                          "r"(b0), "r"(b1));
                }
        }
        stage = stage + 1; if (stage >= NSTG) stage -= NSTG;
    }

    // epilogue: scale by 30, scatter to routed token rows
    float* outp = out + out_off;
    int g = lane >> 2, t4 = lane & 3;
    #pragma unroll
    for (int mt = 0; mt < 2; mt++) {
        #pragma unroll
        for (int h = 0; h < 2; h++) {
            int rl = wm + mt * 16 + h * 8 + g;
            if (rl < mcnt) {
                float* rowp = outp + (size_t)srow[rl] * NCLS;
                #pragma unroll
                for (int nt = 0; nt < 8; nt++) {
                    int c = n0 + wn + nt * 8 + t4 * 2;
                    if (c < NCLS) {
                        float2 vv;
                        vv.x = acc[mt][nt][h * 2]     * SCALE_F;
                        vv.y = acc[mt][nt][h * 2 + 1] * SCALE_F;
                        *reinterpret_cast<float2*>(rowp + c) = vv;
                    }
                }
            }
        }
    }
}

// ---------------- launch ----------------
extern "C" void kernel_launch(void* const* d_in, const int* in_sizes, int n_in,
                              void* d_out, int out_size) {
    const float* x  = (const float*)d_in[0];
    const float* wc = (const float*)d_in[1];
    const float* w0 = (const float*)d_in[2];
    const float* w1 = (const float*)d_in[3];
    const float* w2 = (const float*)d_in[4];
    float* out = (float*)d_out;

    // decode output layout from out_size (outputs concatenated, cast to f32)
    const long Bl = B_TOK;
    long coarse_off = -1, sel_off = -1, out_off = -1;
    long os = (long)out_size;
    if (os == Bl * 1004)      { coarse_off = 0; sel_off = 3 * Bl; out_off = 4 * Bl; }
    else if (os == Bl * 1000) { out_off = 0; }
    else if (os == Bl * 1001) { sel_off = 0; out_off = Bl; }
    else if (os == Bl * 1003) { coarse_off = 0; out_off = 3 * Bl; }
    else if (os == Bl * 3)    { coarse_off = 0; }
    else                      { coarse_off = 0; sel_off = 3 * Bl; out_off = 4 * Bl; }

    cudaFuncSetAttribute(k_gemm, cudaFuncAttributeMaxDynamicSharedMemorySize, SMEM_DYN);

    k_norm_w<<<NEXP * NCLS + NEXP, 128>>>(wc, w0, w1, w2);
    k_coarse_route<<<B_TOK / 8, 256>>>(x, out, coarse_off, sel_off);
    if (out_off >= 0) {
        dim3 grid((NCLS + TN - 1) / TN, (B_TOK + TM - 1) / TM, NEXP);
        k_gemm<<<grid, 256, SMEM_DYN>>>(out, out_off);
    }
}

// round 14
// speedup vs baseline: 1.3760x; 1.3760x over previous
#include <cuda_runtime.h>
#include <cuda_fp16.h>
#include <cstdint>

#define B_TOK 65536
#define DIM   512
#define NCLS  1000
#define NEXP  3
#define SCALE_F 30.0f

#define TM 128
#define TN 128
#define KC 64
#define NCH (DIM / KC)   // 8 k-chunks
#define NSTG 3
#define A_STG_B 16384                       // A stage bytes (128 rows x 128B)
#define STG_BYTES 32768                     // A+B stage bytes
#define SMEM_DYN (NSTG * STG_BYTES + 128)   // 96 KB + align slack

// ---------------- device scratch (static allocation only) ----------------
__device__ __half g_fw[NEXP * NCLS * DIM];        // normalized fine weights, fp16, [e][c][d]
__device__ float  g_cw[NEXP * DIM];               // normalized coarse weights, fp32
__device__ __half g_nx[(size_t)B_TOK * DIM];      // normalized tokens, fp16
__device__ int    g_cnt[NEXP];                    // per-expert token counts
__device__ int    g_idx[NEXP * B_TOK];            // per-expert token index lists

// ---------------- kernel 0: normalize weights ----------------
__global__ void k_norm_w(const float* __restrict__ wc,
                         const float* __restrict__ w0,
                         const float* __restrict__ w1,
                         const float* __restrict__ w2) {
    int r = blockIdx.x;
    int t = threadIdx.x;
    if (r == 0 && t < NEXP) g_cnt[t] = 0;

    const float* src;
    bool fine = (r < NEXP * NCLS);
    if (fine) {
        int e = r / NCLS, c = r - e * NCLS;
        const float* w = (e == 0) ? w0 : ((e == 1) ? w1 : w2);
        src = w + (size_t)c * DIM;
    } else {
        src = wc + (size_t)(r - NEXP * NCLS) * DIM;
    }

    float v[4];
    float ss = 0.f;
    #pragma unroll
    for (int i = 0; i < 4; i++) {
        v[i] = src[t + i * 128];
        ss += v[i] * v[i];
    }
    #pragma unroll
    for (int o = 16; o > 0; o >>= 1) ss += __shfl_xor_sync(0xffffffffu, ss, o);
    __shared__ float red[4];
    if ((t & 31) == 0) red[t >> 5] = ss;
    __syncthreads();
    float tot = red[0] + red[1] + red[2] + red[3];
    float inv = 1.0f / sqrtf(fmaxf(tot, 1e-24f));

    if (fine) {
        __half* dst = g_fw + (size_t)r * DIM;
        #pragma unroll
        for (int i = 0; i < 4; i++) dst[t + i * 128] = __float2half_rn(v[i] * inv);
    } else {
        float* dst = g_cw + (size_t)(r - NEXP * NCLS) * DIM;
        #pragma unroll
        for (int i = 0; i < 4; i++) dst[t + i * 128] = v[i] * inv;
    }
}

// ---------------- kernel 1: coarse logits + routing + fp16 token convert ----------------
// 8 tokens per warp; coarse weight slices cached in registers across tokens.
__global__ void k_coarse_route(const float* __restrict__ x, float* __restrict__ out,
                               long coarse_off, long sel_off) {
    int warp = threadIdx.x >> 5, lane = threadIdx.x & 31;
    int b0 = (blockIdx.x * 8 + warp) * 8;

    const float4* cw4 = reinterpret_cast<const float4*>(g_cw);
    float4 wr0[4], wr1[4], wr2[4];
    #pragma unroll
    for (int j = 0; j < 4; j++) {
        int o = j * 32 + lane;
        wr0[j] = cw4[o];
        wr1[j] = cw4[o + 128];
        wr2[j] = cw4[o + 256];
    }

    for (int t = 0; t < 8; t++) {
        int b = b0 + t;
        const float4* xr = reinterpret_cast<const float4*>(x + (size_t)b * DIM);

        float4 v[4];
        float ss = 0.f, d0 = 0.f, d1 = 0.f, d2 = 0.f;
        #pragma unroll
        for (int j = 0; j < 4; j++) {
            v[j] = xr[j * 32 + lane];
            ss += v[j].x * v[j].x + v[j].y * v[j].y + v[j].z * v[j].z + v[j].w * v[j].w;
            d0 += v[j].x * wr0[j].x + v[j].y * wr0[j].y + v[j].z * wr0[j].z + v[j].w * wr0[j].w;
            d1 += v[j].x * wr1[j].x + v[j].y * wr1[j].y + v[j].z * wr1[j].z + v[j].w * wr1[j].w;
            d2 += v[j].x * wr2[j].x + v[j].y * wr2[j].y + v[j].z * wr2[j].z + v[j].w * wr2[j].w;
        }
        #pragma unroll
        for (int o = 16; o > 0; o >>= 1) {
            ss += __shfl_xor_sync(0xffffffffu, ss, o);
            d0 += __shfl_xor_sync(0xffffffffu, d0, o);
            d1 += __shfl_xor_sync(0xffffffffu, d1, o);
            d2 += __shfl_xor_sync(0xffffffffu, d2, o);
        }
        float inv = 1.0f / sqrtf(fmaxf(ss, 1e-24f));
        float c0 = d0 * inv * SCALE_F;
        float c1 = d1 * inv * SCALE_F;
        float c2 = d2 * inv * SCALE_F;
        int sel = 0; float best = c0;
        if (c1 > best) { best = c1; sel = 1; }
        if (c2 > best) { sel = 2; }

        if (lane == 0) {
            if (coarse_off >= 0) {
                out[coarse_off + (size_t)b * 3 + 0] = c0;
                out[coarse_off + (size_t)b * 3 + 1] = c1;
                out[coarse_off + (size_t)b * 3 + 2] = c2;
            }
            if (sel_off >= 0) out[sel_off + b] = (float)sel;
            int pos = atomicAdd(&g_cnt[sel], 1);
            g_idx[sel * B_TOK + pos] = b;
        }

        __half2* dst = reinterpret_cast<__half2*>(g_nx + (size_t)b * DIM);
        #pragma unroll
        for (int j = 0; j < 4; j++) {
            int o = (j * 32 + lane) * 2;
            dst[o]     = __floats2half2_rn(v[j].x * inv, v[j].y * inv);
            dst[o + 1] = __floats2half2_rn(v[j].z * inv, v[j].w * inv);
        }
    }
}

// ---------------- kernel 2: routed fp16 GEMM (R12: per-expert launch, hoisted addressing) ----------------
__device__ __forceinline__ void cp16(uint32_t dst, const void* src) {
    asm volatile("cp.async.cg.shared.global [%0], [%1], 16;\n" :: "r"(dst), "l"(src));
}
__device__ __forceinline__ void cp_commit() { asm volatile("cp.async.commit_group;\n"); }
template <int N> __device__ __forceinline__ void cp_wait() {
    asm volatile("cp.async.wait_group %0;\n" :: "n"(N));
}
#define LDSM4(f, addr) \
    asm volatile("ldmatrix.sync.aligned.m8n8.x4.shared.b16 {%0,%1,%2,%3}, [%4];" \
        : "=r"((f)[0]), "=r"((f)[1]), "=r"((f)[2]), "=r"((f)[3]) : "r"(addr))

__global__ void __launch_bounds__(256, 2)
k_gemm(float* __restrict__ out, long out_off, int e) {
    extern __shared__ __half sm[];
    __shared__ int srow[TM];

    int cnt = g_cnt[e];
    int m0 = blockIdx.y * TM;
    if (m0 >= cnt) return;
    int n0 = blockIdx.x * TN;
    int mcnt = min(TM, cnt - m0);
    int tid = threadIdx.x;

    if (tid < TM) {
        int mi = m0 + tid;
        srow[tid] = g_idx[e * B_TOK + (mi < cnt ? mi : m0)];
    }
    __syncthreads();

    uint32_t sbase = (uint32_t)__cvta_generic_to_shared(sm);
    sbase = (sbase + 127u) & ~127u;        // 128B-align: XOR swizzle trick exact

    const __half* wbase = g_fw + (size_t)e * NCLS * DIM;

    // ---- hoisted producer addressing: fixed rows per thread, advance by KC per chunk ----
    const __half* asrc[4];
    const __half* bsrc[4];
    uint32_t adst[4], bdst[4];
    #pragma unroll
    for (int i = 0; i < 4; i++) {
        int id = tid + i * 256;
        int r = id >> 3, seg = id & 7;
        asrc[i] = g_nx + (size_t)srow[r] * DIM + seg * 8;
        adst[i] = r * 128 + ((seg ^ (r & 7)) << 4);
        int c = n0 + r; if (c >= NCLS) c = NCLS - 1;   // clamp, store-side guarded
        bsrc[i] = wbase + (size_t)c * DIM + seg * 8;
        bdst[i] = A_STG_B + r * 128 + ((seg ^ (r & 7)) << 4);
    }

    auto load_stage = [&](int s) {          // loads NEXT sequential chunk (ptrs auto-advance)
        uint32_t sa = sbase + s * STG_BYTES;
        #pragma unroll
        for (int i = 0; i < 4; i++) { cp16(sa + adst[i], asrc[i]); asrc[i] += KC; }
        #pragma unroll
        for (int i = 0; i < 4; i++) { cp16(sa + bdst[i], bsrc[i]); bsrc[i] += KC; }
    };

    load_stage(0);      cp_commit();        // chunk 0
    load_stage(1);      cp_commit();        // chunk 1

    int warp = tid >> 5, lane = tid & 31;
    int wm = (warp >> 1) * 32;   // 4 warps along M
    int wn = (warp & 1) * 64;    // 2 warps along N

    // per-thread base byte offsets within a stage (kk=0); per-kk addr = base ^ (kk*32)
    uint32_t aoff[2], boff[4];
    #pragma unroll
    for (int mt = 0; mt < 2; mt++) {
        int row = wm + mt * 16 + (lane & 15);
        int s = lane >> 4;
        aoff[mt] = row * 128 + ((s ^ (row & 7)) << 4);
    }
    #pragma unroll
    for (int bt = 0; bt < 4; bt++) {
        int sub = lane >> 3;
        int n = wn + bt * 16 + ((sub >> 1) << 3) + (lane & 7);
        int s = sub & 1;
        boff[bt] = A_STG_B + n * 128 + ((s ^ (n & 7)) << 4);
    }

    float acc[2][8][4];
    #pragma unroll
    for (int a = 0; a < 2; a++)
        #pragma unroll
        for (int b = 0; b < 8; b++)
            #pragma unroll
            for (int c = 0; c < 4; c++) acc[a][b][c] = 0.f;

    int stage = 0;
    for (int ch = 0; ch < NCH; ch++) {
        cp_wait<1>();
        __syncthreads();      // chunk ch resident; stage we write next is free

        // issue next-next chunk load into the stage freed last iteration
        if (ch + 2 < NCH) {
            int s2 = stage + 2; if (s2 >= NSTG) s2 -= NSTG;
            load_stage(s2);
        }
        cp_commit();          // unconditional: uniform group accounting

        uint32_t sb = sbase + stage * STG_BYTES;
        #pragma unroll
        for (int kk = 0; kk < 4; kk++) {
            uint32_t x = (uint32_t)kk << 5;
            uint32_t af[2][4], bf[4][4];
            #pragma unroll
            for (int mt = 0; mt < 2; mt++) LDSM4(af[mt], (sb + aoff[mt]) ^ x);
            #pragma unroll
            for (int bt = 0; bt < 4; bt++) LDSM4(bf[bt], (sb + boff[bt]) ^ x);
            #pragma unroll
            for (int mt = 0; mt < 2; mt++)
                #pragma unroll
                for (int nt = 0; nt < 8; nt++) {
                    uint32_t b0 = bf[nt >> 1][(nt & 1) * 2];
                    uint32_t b1 = bf[nt >> 1][(nt & 1) * 2 + 1];
                    asm volatile(
                        "mma.sync.aligned.m16n8k16.row.col.f32.f16.f16.f32 "
                        "{%0,%1,%2,%3}, {%4,%5,%6,%7}, {%8,%9}, {%0,%1,%2,%3};"
                        : "+f"(acc[mt][nt][0]), "+f"(acc[mt][nt][1]),
                          "+f"(acc[mt][nt][2]), "+f"(acc[mt][nt][3])
                        : "r"(af[mt][0]), "r"(af[mt][1]),
                          "r"(af[mt][2]), "r"(af[mt][3]),
                          "r"(b0), "r"(b1));
                }
        }
        stage = stage + 1; if (stage >= NSTG) stage -= NSTG;
    }

    // epilogue: scale by 30, scatter to routed token rows
    float* outp = out + out_off;
    int g = lane >> 2, t4 = lane & 3;
    #pragma unroll
    for (int mt = 0; mt < 2; mt++) {
        #pragma unroll
        for (int h = 0; h < 2; h++) {
            int rl = wm + mt * 16 + h * 8 + g;
            if (rl < mcnt) {
                float* rowp = outp + (size_t)srow[rl] * NCLS;
                #pragma unroll
                for (int nt = 0; nt < 8; nt++) {
                    int c = n0 + wn + nt * 8 + t4 * 2;
                    if (c < NCLS) {
                        float2 vv;
                        vv.x = acc[mt][nt][h * 2]     * SCALE_F;
                        vv.y = acc[mt][nt][h * 2 + 1] * SCALE_F;
                        *reinterpret_cast<float2*>(rowp + c) = vv;
                    }
                }
            }
        }
    }
}

// ---------------- launch ----------------
extern "C" void kernel_launch(void* const* d_in, const int* in_sizes, int n_in,
                              void* d_out, int out_size) {
    const float* x  = (const float*)d_in[0];
    const float* wc = (const float*)d_in[1];
    const float* w0 = (const float*)d_in[2];
    const float* w1 = (const float*)d_in[3];
    const float* w2 = (const float*)d_in[4];
    float* out = (float*)d_out;

    // decode output layout from out_size (outputs concatenated, cast to f32)
    const long Bl = B_TOK;
    long coarse_off = -1, sel_off = -1, out_off = -1;
    long os = (long)out_size;
    if (os == Bl * 1004)      { coarse_off = 0; sel_off = 3 * Bl; out_off = 4 * Bl; }
    else if (os == Bl * 1000) { out_off = 0; }
    else if (os == Bl * 1001) { sel_off = 0; out_off = Bl; }
    else if (os == Bl * 1003) { coarse_off = 0; out_off = 3 * Bl; }
    else if (os == Bl * 3)    { coarse_off = 0; }
    else                      { coarse_off = 0; sel_off = 3 * Bl; out_off = 4 * Bl; }

    cudaFuncSetAttribute(k_gemm, cudaFuncAttributeMaxDynamicSharedMemorySize, SMEM_DYN);

    k_norm_w<<<NEXP * NCLS + NEXP, 128>>>(wc, w0, w1, w2);
    k_coarse_route<<<B_TOK / 64, 256>>>(x, out, coarse_off, sel_off);
    if (out_off >= 0) {
        dim3 grid((NCLS + TN - 1) / TN, (B_TOK + TM - 1) / TM, 1);
        k_gemm<<<grid, 256, SMEM_DYN>>>(out, out_off, 0);   // split launches: best measured
        k_gemm<<<grid, 256, SMEM_DYN>>>(out, out_off, 1);   // (R12 = 252.5us); period-5
        k_gemm<<<grid, 256, SMEM_DYN>>>(out, out_off, 2);   // train keeps ncu on k_gemm
    }
}

// round 15
// speedup vs baseline: 1.4312x; 1.0401x over previous
#include <cuda_runtime.h>
#include <cuda_fp16.h>
#include <cstdint>

#define B_TOK 65536
#define DIM   512
#define NCLS  1000
#define NEXP  3
#define SCALE_F 30.0f

#define TM 128
#define TN 128
#define KC 64
#define NCH (DIM / KC)   // 8 k-chunks
#define NSTG 3
#define A_STG_B 16384                       // A stage bytes (128 rows x 128B)
#define STG_BYTES 32768                     // A+B stage bytes
#define SMEM_DYN (NSTG * STG_BYTES + 128)   // 96 KB + align slack

// ---------------- device scratch (static allocation only) ----------------
__device__ __half g_fw[NEXP * NCLS * DIM];        // normalized fine weights, fp16, [e][c][d]
__device__ float  g_cw[NEXP * DIM];               // normalized coarse weights, fp32
__device__ __half g_nx[(size_t)B_TOK * DIM];      // normalized tokens, fp16
__device__ int    g_cnt[NEXP];                    // per-expert token counts
__device__ int    g_idx[NEXP * B_TOK];            // per-expert token index lists

// ---------------- kernel 0: normalize weights ----------------
__global__ void k_norm_w(const float* __restrict__ wc,
                         const float* __restrict__ w0,
                         const float* __restrict__ w1,
                         const float* __restrict__ w2) {
    int r = blockIdx.x;
    int t = threadIdx.x;
    if (r == 0 && t < NEXP) g_cnt[t] = 0;

    const float* src;
    bool fine = (r < NEXP * NCLS);
    if (fine) {
        int e = r / NCLS, c = r - e * NCLS;
        const float* w = (e == 0) ? w0 : ((e == 1) ? w1 : w2);
        src = w + (size_t)c * DIM;
    } else {
        src = wc + (size_t)(r - NEXP * NCLS) * DIM;
    }

    float v[4];
    float ss = 0.f;
    #pragma unroll
    for (int i = 0; i < 4; i++) {
        v[i] = src[t + i * 128];
        ss += v[i] * v[i];
    }
    #pragma unroll
    for (int o = 16; o > 0; o >>= 1) ss += __shfl_xor_sync(0xffffffffu, ss, o);
    __shared__ float red[4];
    if ((t & 31) == 0) red[t >> 5] = ss;
    __syncthreads();
    float tot = red[0] + red[1] + red[2] + red[3];
    float inv = 1.0f / sqrtf(fmaxf(tot, 1e-24f));

    if (fine) {
        __half* dst = g_fw + (size_t)r * DIM;
        #pragma unroll
        for (int i = 0; i < 4; i++) dst[t + i * 128] = __float2half_rn(v[i] * inv);
    } else {
        float* dst = g_cw + (size_t)(r - NEXP * NCLS) * DIM;
        #pragma unroll
        for (int i = 0; i < 4; i++) dst[t + i * 128] = v[i] * inv;
    }
}

// ---------------- kernel 1: coarse logits + routing + fp16 token convert ----------------
__global__ void k_coarse_route(const float* __restrict__ x, float* __restrict__ out,
                               long coarse_off, long sel_off) {
    int warp = threadIdx.x >> 5, lane = threadIdx.x & 31;
    int b = blockIdx.x * 8 + warp;

    const float4* xr = reinterpret_cast<const float4*>(x + (size_t)b * DIM);
    const float4* cw4 = reinterpret_cast<const float4*>(g_cw);

    float4 v[4];
    float ss = 0.f, d0 = 0.f, d1 = 0.f, d2 = 0.f;
    #pragma unroll
    for (int j = 0; j < 4; j++) {
        int o = j * 32 + lane;
        v[j] = xr[o];
        float4 c0 = cw4[o];
        float4 c1 = cw4[o + 128];
        float4 c2 = cw4[o + 256];
        ss += v[j].x * v[j].x + v[j].y * v[j].y + v[j].z * v[j].z + v[j].w * v[j].w;
        d0 += v[j].x * c0.x + v[j].y * c0.y + v[j].z * c0.z + v[j].w * c0.w;
        d1 += v[j].x * c1.x + v[j].y * c1.y + v[j].z * c1.z + v[j].w * c1.w;
        d2 += v[j].x * c2.x + v[j].y * c2.y + v[j].z * c2.z + v[j].w * c2.w;
    }
    #pragma unroll
    for (int o = 16; o > 0; o >>= 1) {
        ss += __shfl_xor_sync(0xffffffffu, ss, o);
        d0 += __shfl_xor_sync(0xffffffffu, d0, o);
        d1 += __shfl_xor_sync(0xffffffffu, d1, o);
        d2 += __shfl_xor_sync(0xffffffffu, d2, o);
    }
    float inv = 1.0f / sqrtf(fmaxf(ss, 1e-24f));
    float c0 = d0 * inv * SCALE_F;
    float c1 = d1 * inv * SCALE_F;
    float c2 = d2 * inv * SCALE_F;
    int sel = 0; float best = c0;
    if (c1 > best) { best = c1; sel = 1; }
    if (c2 > best) { sel = 2; }

    if (lane == 0) {
        if (coarse_off >= 0) {
            out[coarse_off + (size_t)b * 3 + 0] = c0;
            out[coarse_off + (size_t)b * 3 + 1] = c1;
            out[coarse_off + (size_t)b * 3 + 2] = c2;
        }
        if (sel_off >= 0) out[sel_off + b] = (float)sel;
        int pos = atomicAdd(&g_cnt[sel], 1);
        g_idx[sel * B_TOK + pos] = b;
    }

    __half2* dst = reinterpret_cast<__half2*>(g_nx + (size_t)b * DIM);
    #pragma unroll
    for (int j = 0; j < 4; j++) {
        int o = (j * 32 + lane) * 2;
        dst[o]     = __floats2half2_rn(v[j].x * inv, v[j].y * inv);
        dst[o + 1] = __floats2half2_rn(v[j].z * inv, v[j].w * inv);
    }
}

// ---------------- kernel 2: routed fp16 GEMM (R12: per-expert, hoisted addressing) ----------------
__device__ __forceinline__ void cp16(uint32_t dst, const void* src) {
    asm volatile("cp.async.cg.shared.global [%0], [%1], 16;\n" :: "r"(dst), "l"(src));
}
__device__ __forceinline__ void cp_commit() { asm volatile("cp.async.commit_group;\n"); }
template <int N> __device__ __forceinline__ void cp_wait() {
    asm volatile("cp.async.wait_group %0;\n" :: "n"(N));
}
#define LDSM4(f, addr) \
    asm volatile("ldmatrix.sync.aligned.m8n8.x4.shared.b16 {%0,%1,%2,%3}, [%4];" \
        : "=r"((f)[0]), "=r"((f)[1]), "=r"((f)[2]), "=r"((f)[3]) : "r"(addr))

__global__ void __launch_bounds__(256, 2)
k_gemm(float* __restrict__ out, long out_off, int e) {
    extern __shared__ __half sm[];
    __shared__ int srow[TM];

    int cnt = g_cnt[e];
    int m0 = blockIdx.y * TM;
    if (m0 >= cnt) return;
    int n0 = blockIdx.x * TN;
    int mcnt = min(TM, cnt - m0);
    int tid = threadIdx.x;

    if (tid < TM) {
        int mi = m0 + tid;
        srow[tid] = g_idx[e * B_TOK + (mi < cnt ? mi : m0)];
    }
    __syncthreads();

    uint32_t sbase = (uint32_t)__cvta_generic_to_shared(sm);
    sbase = (sbase + 127u) & ~127u;        // 128B-align: XOR swizzle trick exact

    const __half* wbase = g_fw + (size_t)e * NCLS * DIM;

    // ---- hoisted producer addressing: fixed rows per thread, advance by KC per chunk ----
    const __half* asrc[4];
    const __half* bsrc[4];
    uint32_t adst[4], bdst[4];
    #pragma unroll
    for (int i = 0; i < 4; i++) {
        int id = tid + i * 256;
        int r = id >> 3, seg = id & 7;
        asrc[i] = g_nx + (size_t)srow[r] * DIM + seg * 8;
        adst[i] = r * 128 + ((seg ^ (r & 7)) << 4);
        int c = n0 + r; if (c >= NCLS) c = NCLS - 1;   // clamp, store-side guarded
        bsrc[i] = wbase + (size_t)c * DIM + seg * 8;
        bdst[i] = A_STG_B + r * 128 + ((seg ^ (r & 7)) << 4);
    }

    auto load_stage = [&](int s) {          // loads NEXT sequential chunk (ptrs auto-advance)
        uint32_t sa = sbase + s * STG_BYTES;
        #pragma unroll
        for (int i = 0; i < 4; i++) { cp16(sa + adst[i], asrc[i]); asrc[i] += KC; }
        #pragma unroll
        for (int i = 0; i < 4; i++) { cp16(sa + bdst[i], bsrc[i]); bsrc[i] += KC; }
    };

    load_stage(0);      cp_commit();        // chunk 0
    load_stage(1);      cp_commit();        // chunk 1

    int warp = tid >> 5, lane = tid & 31;
    int wm = (warp >> 1) * 32;   // 4 warps along M
    int wn = (warp & 1) * 64;    // 2 warps along N

    // per-thread base byte offsets within a stage (kk=0); per-kk addr = base ^ (kk*32)
    uint32_t aoff[2], boff[4];
    #pragma unroll
    for (int mt = 0; mt < 2; mt++) {
        int row = wm + mt * 16 + (lane & 15);
        int s = lane >> 4;
        aoff[mt] = row * 128 + ((s ^ (row & 7)) << 4);
    }
    #pragma unroll
    for (int bt = 0; bt < 4; bt++) {
        int sub = lane >> 3;
        int n = wn + bt * 16 + ((sub >> 1) << 3) + (lane & 7);
        int s = sub & 1;
        boff[bt] = A_STG_B + n * 128 + ((s ^ (n & 7)) << 4);
    }

    float acc[2][8][4];
    #pragma unroll
    for (int a = 0; a < 2; a++)
        #pragma unroll
        for (int b = 0; b < 8; b++)
            #pragma unroll
            for (int c = 0; c < 4; c++) acc[a][b][c] = 0.f;

    int stage = 0;
    for (int ch = 0; ch < NCH; ch++) {
        cp_wait<1>();
        __syncthreads();      // chunk ch resident; stage we write next is free

        // issue next-next chunk load into the stage freed last iteration
        if (ch + 2 < NCH) {
            int s2 = stage + 2; if (s2 >= NSTG) s2 -= NSTG;
            load_stage(s2);
        }
        cp_commit();          // unconditional: uniform group accounting

        uint32_t sb = sbase + stage * STG_BYTES;
        #pragma unroll
        for (int kk = 0; kk < 4; kk++) {
            uint32_t x = (uint32_t)kk << 5;
            uint32_t af[2][4], bf[4][4];
            #pragma unroll
            for (int mt = 0; mt < 2; mt++) LDSM4(af[mt], (sb + aoff[mt]) ^ x);
            #pragma unroll
            for (int bt = 0; bt < 4; bt++) LDSM4(bf[bt], (sb + boff[bt]) ^ x);
            #pragma unroll
            for (int mt = 0; mt < 2; mt++)
                #pragma unroll
                for (int nt = 0; nt < 8; nt++) {
                    uint32_t b0 = bf[nt >> 1][(nt & 1) * 2];
                    uint32_t b1 = bf[nt >> 1][(nt & 1) * 2 + 1];
                    asm volatile(
                        "mma.sync.aligned.m16n8k16.row.col.f32.f16.f16.f32 "
                        "{%0,%1,%2,%3}, {%4,%5,%6,%7}, {%8,%9}, {%0,%1,%2,%3};"
                        : "+f"(acc[mt][nt][0]), "+f"(acc[mt][nt][1]),
                          "+f"(acc[mt][nt][2]), "+f"(acc[mt][nt][3])
                        : "r"(af[mt][0]), "r"(af[mt][1]),
                          "r"(af[mt][2]), "r"(af[mt][3]),
                          "r"(b0), "r"(b1));
                }
        }
        stage = stage + 1; if (stage >= NSTG) stage -= NSTG;
    }

    // epilogue: scale by 30, scatter to routed token rows
    float* outp = out + out_off;
    int g = lane >> 2, t4 = lane & 3;
    #pragma unroll
    for (int mt = 0; mt < 2; mt++) {
        #pragma unroll
        for (int h = 0; h < 2; h++) {
            int rl = wm + mt * 16 + h * 8 + g;
            if (rl < mcnt) {
                float* rowp = outp + (size_t)srow[rl] * NCLS;
                #pragma unroll
                for (int nt = 0; nt < 8; nt++) {
                    int c = n0 + wn + nt * 8 + t4 * 2;
                    if (c < NCLS) {
                        float2 vv;
                        vv.x = acc[mt][nt][h * 2]     * SCALE_F;
                        vv.y = acc[mt][nt][h * 2 + 1] * SCALE_F;
                        *reinterpret_cast<float2*>(rowp + c) = vv;
                    }
                }
            }
        }
    }
}

// ---------------- launch: fork the 3 expert GEMMs onto parallel streams ----------------
extern "C" void kernel_launch(void* const* d_in, const int* in_sizes, int n_in,
                              void* d_out, int out_size) {
    const float* x  = (const float*)d_in[0];
    const float* wc = (const float*)d_in[1];
    const float* w0 = (const float*)d_in[2];
    const float* w1 = (const float*)d_in[3];
    const float* w2 = (const float*)d_in[4];
    float* out = (float*)d_out;

    // decode output layout from out_size (outputs concatenated, cast to f32)
    const long Bl = B_TOK;
    long coarse_off = -1, sel_off = -1, out_off = -1;
    long os = (long)out_size;
    if (os == Bl * 1004)      { coarse_off = 0; sel_off = 3 * Bl; out_off = 4 * Bl; }
    else if (os == Bl * 1000) { out_off = 0; }
    else if (os == Bl * 1001) { sel_off = 0; out_off = Bl; }
    else if (os == Bl * 1003) { coarse_off = 0; out_off = 3 * Bl; }
    else if (os == Bl * 3)    { coarse_off = 0; }
    else                      { coarse_off = 0; sel_off = 3 * Bl; out_off = 4 * Bl; }

    // streams/events created once, on the (uncaptured) correctness call; reused in capture.
    static cudaStream_t st[NEXP] = {};
    static cudaEvent_t  evFork = nullptr, evJ[NEXP] = {};
    if (evFork == nullptr) {
        for (int i = 0; i < NEXP; i++)
            cudaStreamCreateWithFlags(&st[i], cudaStreamNonBlocking);
        cudaEventCreateWithFlags(&evFork, cudaEventDisableTiming);
        for (int i = 0; i < NEXP; i++)
            cudaEventCreateWithFlags(&evJ[i], cudaEventDisableTiming);
    }

    cudaFuncSetAttribute(k_gemm, cudaFuncAttributeMaxDynamicSharedMemorySize, SMEM_DYN);

    k_norm_w<<<NEXP * NCLS + NEXP, 128>>>(wc, w0, w1, w2);
    k_coarse_route<<<B_TOK / 8, 256>>>(x, out, coarse_off, sel_off);

    if (out_off >= 0) {
        dim3 grid((NCLS + TN - 1) / TN, (B_TOK + TM - 1) / TM, 1);
        cudaEventRecord(evFork, 0);
        for (int e = 0; e < NEXP; e++) {
            cudaStreamWaitEvent(st[e], evFork, 0);
            k_gemm<<<grid, 256, SMEM_DYN, st[e]>>>(out, out_off, e);
            cudaEventRecord(evJ[e], st[e]);
        }
        for (int e = 0; e < NEXP; e++)
            cudaStreamWaitEvent(0, evJ[e], 0);
    }
}